// round 5
// baseline (speedup 1.0000x reference)
#include <cuda_runtime.h>
#include <math.h>

#define B_  32
#define T_  2048
#define D_  512
#define H_  512
#define G4_ 2048   // 4*H

// ---------------- device scratch ----------------
__device__ float g_xp[(size_t)B_ * T_ * G4_];   // x_proj scratch [B][T][4H]
__device__ float g_h[2][B_ * H_];               // double-buffered hidden state
__device__ unsigned int g_ctr;                  // grid barrier counter

typedef unsigned long long ull;

// ---------------- packed f32x2 helpers ----------------
__device__ __forceinline__ ull pk(float lo, float hi) {
    ull r;
    asm("mov.b64 %0, {%1, %2};" : "=l"(r) : "f"(lo), "f"(hi));
    return r;
}
__device__ __forceinline__ ull fma2(ull a, ull b, ull c) {
    ull d;
    asm("fma.rn.f32x2 %0, %1, %2, %3;" : "=l"(d) : "l"(a), "l"(b), "l"(c));
    return d;
}

// ---------------- grid barrier primitives ----------------
__device__ __forceinline__ void red_add_release(unsigned int* p, unsigned int v) {
    asm volatile("red.release.gpu.add.u32 [%0], %1;" :: "l"(p), "r"(v) : "memory");
}
__device__ __forceinline__ unsigned int ld_acquire(unsigned int* p) {
    unsigned int v;
    asm volatile("ld.acquire.gpu.u32 %0, [%1];" : "=r"(v) : "l"(p) : "memory");
    return v;
}

// =====================================================================
// Phase 1: x_proj[65536, 2048] = inputs[65536,512] @ Wi[512,2048]
// =====================================================================
#define BM 128
#define BN 128
#define BKK 8

__global__ __launch_bounds__(256) void gemm_xproj(const float* __restrict__ A,
                                                  const float* __restrict__ Bw) {
    __shared__ float As[BKK][BM + 4];
    __shared__ float Bs[BKK][BN + 4];

    const int tid = threadIdx.x;
    const int m0 = blockIdx.y * BM;
    const int n0 = blockIdx.x * BN;
    const int tx = tid & 15;
    const int ty = tid >> 4;

    const int arow = tid >> 1;
    const int akq  = (tid & 1) * 4;
    const int bkr  = tid >> 5;
    const int bq   = tid & 31;

    ull acc[8][4];
#pragma unroll
    for (int i = 0; i < 8; i++)
#pragma unroll
        for (int j = 0; j < 4; j++) acc[i][j] = 0ull;

    for (int kt = 0; kt < D_ / BKK; ++kt) {
        float4 av = *(const float4*)&A[(size_t)(m0 + arow) * D_ + kt * BKK + akq];
        As[akq + 0][arow] = av.x;
        As[akq + 1][arow] = av.y;
        As[akq + 2][arow] = av.z;
        As[akq + 3][arow] = av.w;
        float4 bv = *(const float4*)&Bw[(size_t)(kt * BKK + bkr) * G4_ + n0 + bq * 4];
        *(float4*)&Bs[bkr][bq * 4] = bv;
        __syncthreads();

#pragma unroll
        for (int k = 0; k < BKK; ++k) {
            float4 a0 = *(const float4*)&As[k][ty * 8];
            float4 a1 = *(const float4*)&As[k][ty * 8 + 4];
            const ull* bp = (const ull*)&Bs[k][tx * 8];
            ull b0 = bp[0], b1 = bp[1], b2 = bp[2], b3 = bp[3];
            float ar[8] = {a0.x, a0.y, a0.z, a0.w, a1.x, a1.y, a1.z, a1.w};
#pragma unroll
            for (int i = 0; i < 8; i++) {
                ull a2 = pk(ar[i], ar[i]);
                acc[i][0] = fma2(a2, b0, acc[i][0]);
                acc[i][1] = fma2(a2, b1, acc[i][1]);
                acc[i][2] = fma2(a2, b2, acc[i][2]);
                acc[i][3] = fma2(a2, b3, acc[i][3]);
            }
        }
        __syncthreads();
    }

#pragma unroll
    for (int i = 0; i < 8; i++) {
        size_t row = (size_t)(m0 + ty * 8 + i);
#pragma unroll
        for (int j = 0; j < 4; j++) {
            *(float2*)&g_xp[row * G4_ + n0 + tx * 8 + 2 * j] = *(float2*)&acc[i][j];
        }
    }
}

// =====================================================================
// Init
// =====================================================================
__global__ void init_kernel(const float* __restrict__ h0) {
    int i = blockIdx.x * blockDim.x + threadIdx.x;
    if (i == 0) g_ctr = 0u;
    if (i < B_ * H_) g_h[0][i] = h0[i];
}

// =====================================================================
// Phase 2 (v5): 2-D partitioned persistent LSTM.
// 128 blocks = 4 batch-groups x 32 col-groups. Block owns 8 batches x
// 16 h-cols (64 z-cols incl. gates). h staged per step: only 16 KB/block.
// Thread (ko, bgp, cq): 4 z-cols x 4 batches x 64 k's.
// =====================================================================
#define WST 516     // w_s / h_s row stride (floats): 16B-aligned, bank-spread
#define PST 68      // part innermost stride: 16B-aligned

__device__ __forceinline__ float sigf(float x) {
    return __fdividef(1.0f, 1.0f + __expf(-x));
}
__device__ __forceinline__ float tanhf_fast(float x) {
    return __fdividef(2.0f, 1.0f + __expf(-2.0f * x)) - 1.0f;
}

extern __shared__ float smem_dyn[];

__global__ __launch_bounds__(256, 1) void lstm_seq(const float* __restrict__ c0,
                                                   const float* __restrict__ bias,
                                                   const float* __restrict__ Wh,
                                                   float* __restrict__ out) {
    // ---- carve dynamic smem ----
    float* w_s  = smem_dyn;                        // [64][WST]   129.0 KB
    float* h_s  = w_s + 64 * WST;                  // [8][WST]     16.1 KB
    float* part = h_s + 8 * WST;                   // [8][8][PST]  17.0 KB
    float* z_s  = part + 8 * 8 * PST;              // [64][9]       2.3 KB
    float* c_s  = z_s + 64 * 9;                    // [8][16]
    float* b_s  = c_s + 8 * 16;                    // [64]

    const int tid = threadIdx.x;
    const int bl  = blockIdx.x;                    // 0..127
    const unsigned int nblk = gridDim.x;

    const int cg   = bl & 31;                      // col group
    const int bgrp = bl >> 5;                      // batch group
    const int col0 = cg * 16;
    const int gb0  = bgrp * 8;

    // ---- compute mapping: tid = ko*32 + bgp*16 + cq ----
    const int cq  = tid & 15;                      // z-col quad 0..15
    const int bgp = (tid >> 4) & 1;                // batch half 0..1
    const int ko  = tid >> 5;                      // k octant 0..7
    const int k0  = ko * 64;
    const int zb  = cq * 4;                        // first owned z-col
    const int bb0 = bgp * 4;                       // first owned local batch

    // ---- reduce mapping: tid = rb*32 + zcp ----
    const int rb   = tid >> 5;                     // local batch 0..7
    const int zc0  = 2 * (tid & 31);               // z-col pair
    const int gzc0 = (zc0 >> 4) * H_ + col0 + (zc0 & 15);

    // ---- load Wh slice, bias, c0 ----
    for (int idx = tid; idx < 64 * 512; idx += 256) {
        int k  = idx >> 6;
        int zc = idx & 63;
        int gcol = (zc >> 4) * H_ + col0 + (zc & 15);
        w_s[zc * WST + k] = Wh[(size_t)k * G4_ + gcol];
    }
    if (tid < 64) b_s[tid] = bias[(tid >> 4) * H_ + col0 + (tid & 15)];
    if (tid < 128) {
        int b = tid >> 4, j = tid & 15;
        c_s[b * 16 + j] = c0[(gb0 + b) * H_ + col0 + j];
    }
    __syncthreads();

    const float* xp_base = g_xp + (size_t)(gb0 + rb) * T_ * G4_ + gzc0;
    const float  bsz0 = b_s[zc0];
    const float  bsz1 = b_s[zc0 + 1];

    int par = 0;
    for (int t = 0; t < T_; ++t) {
        // ---- stage h slice: 8 batches x 512 = 1024 float4, 4/thread ----
        const float* hsrc = g_h[par] + gb0 * H_;
        float4 hreg[4];
#pragma unroll
        for (int i = 0; i < 4; ++i)
            hreg[i] = __ldcg((const float4*)(hsrc + (tid + i * 256) * 4));
        float2 xpv = __ldcs((const float2*)(xp_base + (size_t)t * G4_));
#pragma unroll
        for (int i = 0; i < 4; ++i) {
            int idx4 = tid + i * 256;
            int b  = idx4 >> 7;
            int k4 = idx4 & 127;
            *(float4*)&h_s[b * WST + k4 * 4] = hreg[i];
        }
        __syncthreads();

        // ---- dot products: 4 z-cols x 4 batches x 64 k ----
        ull acc[4][4];                              // [j][bi]
#pragma unroll
        for (int j = 0; j < 4; ++j)
#pragma unroll
            for (int bi = 0; bi < 4; ++bi) acc[j][bi] = 0ull;

#pragma unroll 4
        for (int kk = 0; kk < 64; kk += 4) {
            const int k = k0 + kk;
            float4 wv[4], hv[4];
#pragma unroll
            for (int j = 0; j < 4; ++j)
                wv[j] = *(const float4*)&w_s[(zb + j) * WST + k];   // 16-lane bcast
#pragma unroll
            for (int bi = 0; bi < 4; ++bi)
                hv[bi] = *(const float4*)&h_s[(bb0 + bi) * WST + k];
#pragma unroll
            for (int j = 0; j < 4; ++j) {
                ull w01 = ((const ull*)&wv[j])[0], w23 = ((const ull*)&wv[j])[1];
#pragma unroll
                for (int bi = 0; bi < 4; ++bi) {
                    ull h01 = ((const ull*)&hv[bi])[0], h23 = ((const ull*)&hv[bi])[1];
                    acc[j][bi] = fma2(h01, w01, acc[j][bi]);
                    acc[j][bi] = fma2(h23, w23, acc[j][bi]);
                }
            }
        }

        // ---- hadd over k-parity, stash partials ----
#pragma unroll
        for (int bi = 0; bi < 4; ++bi) {
            float4 pr;
            float2 a0 = *(float2*)&acc[0][bi];
            float2 a1 = *(float2*)&acc[1][bi];
            float2 a2 = *(float2*)&acc[2][bi];
            float2 a3 = *(float2*)&acc[3][bi];
            pr.x = a0.x + a0.y;
            pr.y = a1.x + a1.y;
            pr.z = a2.x + a2.y;
            pr.w = a3.x + a3.y;
            *(float4*)&part[(ko * 8 + bb0 + bi) * PST + zb] = pr;
        }
        __syncthreads();

        // ---- reduce 8 k-octants + xp + bias -> z ----
        {
            float s0 = bsz0 + xpv.x;
            float s1 = bsz1 + xpv.y;
#pragma unroll
            for (int o = 0; o < 8; ++o) {
                float2 p = *(const float2*)&part[(o * 8 + rb) * PST + zc0];
                s0 += p.x;
                s1 += p.y;
            }
            z_s[zc0 * 9 + rb]       = s0;
            z_s[(zc0 + 1) * 9 + rb] = s1;
        }
        __syncthreads();

        // ---- gates: 128 threads = 8 b x 16 cols ----
        if (tid < 128) {
            int b = tid >> 4, j = tid & 15;
            float zi = z_s[j * 9 + b];
            float zf = z_s[(16 + j) * 9 + b];
            float zg = z_s[(32 + j) * 9 + b];
            float zo = z_s[(48 + j) * 9 + b];
            float cn = sigf(zf) * c_s[b * 16 + j] + sigf(zi) * tanhf_fast(zg);
            float hn = sigf(zo) * tanhf_fast(cn);
            c_s[b * 16 + j] = cn;
            g_h[par ^ 1][(gb0 + b) * H_ + col0 + j] = hn;
            __stcs(&out[((size_t)(gb0 + b) * T_ + t) * H_ + col0 + j], hn);
        }
        __syncthreads();

        // ---- grid barrier ----
        if (tid == 0) {
            red_add_release(&g_ctr, 1u);
            unsigned int tgt = (unsigned int)(t + 1) * nblk;
            while (ld_acquire(&g_ctr) < tgt) { }
        }
        __syncthreads();
        par ^= 1;
    }
}

// =====================================================================
// launch
// =====================================================================
#define LSTM_SMEM_BYTES ((64 * WST + 8 * WST + 8 * 8 * PST + 64 * 9 + 8 * 16 + 64) * 4)

extern "C" void kernel_launch(void* const* d_in, const int* in_sizes, int n_in,
                              void* d_out, int out_size) {
    const float* inputs = (const float*)d_in[0];
    // d_in[1] = input_paddings (unused: all tokens valid)
    const float* c0   = (const float*)d_in[2];
    const float* h0   = (const float*)d_in[3];
    const float* Wi   = (const float*)d_in[4];
    const float* Wh   = (const float*)d_in[5];
    const float* bias = (const float*)d_in[6];
    float* out = (float*)d_out;

    cudaFuncSetAttribute(lstm_seq, cudaFuncAttributeMaxDynamicSharedMemorySize,
                         LSTM_SMEM_BYTES);

    dim3 g1(G4_ / BN, (B_ * T_) / BM);   // 16 x 512
    gemm_xproj<<<g1, 256>>>(inputs, Wi);
    init_kernel<<<64, 256>>>(h0);
    lstm_seq<<<128, 256, LSTM_SMEM_BYTES>>>(c0, bias, Wh, out);
}

// round 7
// speedup vs baseline: 1.5290x; 1.5290x over previous
#include <cuda_runtime.h>
#include <math.h>

#define B_  32
#define T_  2048
#define D_  512
#define H_  512
#define G4_ 2048   // 4*H

// ---------------- device scratch ----------------
__device__ float g_xp[(size_t)B_ * T_ * G4_];   // x_proj scratch [B][T][4H]
__device__ float g_h[2][B_ * H_];               // double-buffered hidden state
__device__ unsigned int g_ctr;                  // grid barrier counter

typedef unsigned long long ull;

// ---------------- packed f32x2 helpers ----------------
__device__ __forceinline__ ull pk(float lo, float hi) {
    ull r;
    asm("mov.b64 %0, {%1, %2};" : "=l"(r) : "f"(lo), "f"(hi));
    return r;
}
__device__ __forceinline__ ull fma2(ull a, ull b, ull c) {
    ull d;
    asm("fma.rn.f32x2 %0, %1, %2, %3;" : "=l"(d) : "l"(a), "l"(b), "l"(c));
    return d;
}

// ---------------- grid barrier primitives ----------------
__device__ __forceinline__ void red_add_release(unsigned int* p, unsigned int v) {
    asm volatile("red.release.gpu.add.u32 [%0], %1;" :: "l"(p), "r"(v) : "memory");
}
__device__ __forceinline__ unsigned int ld_acquire(unsigned int* p) {
    unsigned int v;
    asm volatile("ld.acquire.gpu.u32 %0, [%1];" : "=r"(v) : "l"(p) : "memory");
    return v;
}

// =====================================================================
// Phase 1: x_proj[65536, 2048] = inputs[65536,512] @ Wi[512,2048]
// =====================================================================
#define BM 128
#define BN 128
#define BKK 8

__global__ __launch_bounds__(256) void gemm_xproj(const float* __restrict__ A,
                                                  const float* __restrict__ Bw) {
    __shared__ float As[BKK][BM + 4];
    __shared__ float Bs[BKK][BN + 4];

    const int tid = threadIdx.x;
    const int m0 = blockIdx.y * BM;
    const int n0 = blockIdx.x * BN;
    const int tx = tid & 15;
    const int ty = tid >> 4;

    const int arow = tid >> 1;
    const int akq  = (tid & 1) * 4;
    const int bkr  = tid >> 5;
    const int bq   = tid & 31;

    ull acc[8][4];
#pragma unroll
    for (int i = 0; i < 8; i++)
#pragma unroll
        for (int j = 0; j < 4; j++) acc[i][j] = 0ull;

    for (int kt = 0; kt < D_ / BKK; ++kt) {
        float4 av = *(const float4*)&A[(size_t)(m0 + arow) * D_ + kt * BKK + akq];
        As[akq + 0][arow] = av.x;
        As[akq + 1][arow] = av.y;
        As[akq + 2][arow] = av.z;
        As[akq + 3][arow] = av.w;
        float4 bv = *(const float4*)&Bw[(size_t)(kt * BKK + bkr) * G4_ + n0 + bq * 4];
        *(float4*)&Bs[bkr][bq * 4] = bv;
        __syncthreads();

#pragma unroll
        for (int k = 0; k < BKK; ++k) {
            float4 a0 = *(const float4*)&As[k][ty * 8];
            float4 a1 = *(const float4*)&As[k][ty * 8 + 4];
            const ull* bp = (const ull*)&Bs[k][tx * 8];
            ull b0 = bp[0], b1 = bp[1], b2 = bp[2], b3 = bp[3];
            float ar[8] = {a0.x, a0.y, a0.z, a0.w, a1.x, a1.y, a1.z, a1.w};
#pragma unroll
            for (int i = 0; i < 8; i++) {
                ull a2 = pk(ar[i], ar[i]);
                acc[i][0] = fma2(a2, b0, acc[i][0]);
                acc[i][1] = fma2(a2, b1, acc[i][1]);
                acc[i][2] = fma2(a2, b2, acc[i][2]);
                acc[i][3] = fma2(a2, b3, acc[i][3]);
            }
        }
        __syncthreads();
    }

#pragma unroll
    for (int i = 0; i < 8; i++) {
        size_t row = (size_t)(m0 + ty * 8 + i);
#pragma unroll
        for (int j = 0; j < 4; j++) {
            *(float2*)&g_xp[row * G4_ + n0 + tx * 8 + 2 * j] = *(float2*)&acc[i][j];
        }
    }
}

// =====================================================================
// Init
// =====================================================================
__global__ void init_kernel(const float* __restrict__ h0) {
    int i = blockIdx.x * blockDim.x + threadIdx.x;
    if (i == 0) g_ctr = 0u;
    if (i < B_ * H_) g_h[0][i] = h0[i];
}

// =====================================================================
// Phase 2 (v6): weights live in REGISTERS.
// 128 blocks = 4 batch-groups x 32 col-groups; block: 8 batches x 16 h-cols.
// 256 threads = 8 k-octants x 32 zc-pairs.
// Thread: 2 z-cols x 64 k of Wh in 64 f32x2 regs, covers all 8 batches.
// Per-step smem traffic: h 16KB + partials only. fma floor 2048 cyc/SMSP.
// =====================================================================
#define HST 516     // h_s row stride (floats): 16B-aligned, bank-spread
#define PST 68      // part row stride

__device__ __forceinline__ float sigf(float x) {
    return __fdividef(1.0f, 1.0f + __expf(-x));
}
__device__ __forceinline__ float tanhf_fast(float x) {
    return __fdividef(2.0f, 1.0f + __expf(-2.0f * x)) - 1.0f;
}

__global__ __launch_bounds__(256, 1) void lstm_seq(const float* __restrict__ c0,
                                                   const float* __restrict__ bias,
                                                   const float* __restrict__ Wh,
                                                   float* __restrict__ out) {
    __shared__ __align__(16) float h_s[8 * HST];        // 16.5 KB
    __shared__ __align__(16) float part[64 * PST];      // 17.4 KB [ko*8+bi][zc]
    __shared__ float z_s[64 * 9];                       // [zc][b]
    __shared__ float c_s[8 * 16];
    __shared__ float b_s[64];

    const int tid = threadIdx.x;
    const int bl  = blockIdx.x;                    // 0..127
    const unsigned int nblk = gridDim.x;

    const int cg   = bl & 31;                      // col group
    const int bgrp = bl >> 5;                      // batch group
    const int col0 = cg * 16;
    const int gb0  = bgrp * 8;

    // ---- compute mapping: tid = ko*32 + zcp ----
    const int zcp = tid & 31;                      // zc pair 0..31
    const int ko  = tid >> 5;                      // k octant 0..7 (= warp)
    const int k0  = ko * 64;
    const int zct = 2 * zcp;                       // local z-col (even)

    // ---- reduce mapping: same lane layout ----
    const int rb   = tid >> 5;                     // local batch 0..7
    const int zc0r = 2 * (tid & 31);
    const int gzc0 = (zc0r >> 4) * H_ + col0 + (zc0r & 15);

    // ---- one-time: Wh slice -> registers (64 ull = 2 cols x 64 k) ----
    ull wreg[2][32];
    {
        const int gcolA = (zct >> 4) * H_ + col0 + (zct & 15);
        const int gcolB = ((zct + 1) >> 4) * H_ + col0 + ((zct + 1) & 15);
#pragma unroll
        for (int kk = 0; kk < 64; kk += 2) {
            float a0 = Wh[(size_t)(k0 + kk) * G4_ + gcolA];
            float a1 = Wh[(size_t)(k0 + kk + 1) * G4_ + gcolA];
            float b0 = Wh[(size_t)(k0 + kk) * G4_ + gcolB];
            float b1 = Wh[(size_t)(k0 + kk + 1) * G4_ + gcolB];
            wreg[0][kk >> 1] = pk(a0, a1);
            wreg[1][kk >> 1] = pk(b0, b1);
        }
    }
    if (tid < 64) b_s[tid] = bias[(tid >> 4) * H_ + col0 + (tid & 15)];
    if (tid < 128) {
        int b = tid >> 4, j = tid & 15;
        c_s[b * 16 + j] = c0[(gb0 + b) * H_ + col0 + j];
    }
    __syncthreads();

    const float* xp_base = g_xp + (size_t)(gb0 + rb) * T_ * G4_ + gzc0;
    const float  bsz0 = b_s[zc0r];
    const float  bsz1 = b_s[zc0r + 1];

    int par = 0;
    for (int t = 0; t < T_; ++t) {
        // ---- stage h slice: 8 batches x 512 f = 1024 float4, 4/thread ----
        const float* hsrc = g_h[par] + gb0 * H_;
        float4 hreg[4];
#pragma unroll
        for (int i = 0; i < 4; ++i)
            hreg[i] = __ldcg((const float4*)(hsrc + (tid + i * 256) * 4));
        float2 xpv = __ldcs((const float2*)(xp_base + (size_t)t * G4_));
#pragma unroll
        for (int i = 0; i < 4; ++i) {
            int idx4 = tid + i * 256;
            int b  = idx4 >> 7;
            int k4 = idx4 & 127;
            *(float4*)&h_s[b * HST + k4 * 4] = hreg[i];
        }
        __syncthreads();

        // ---- dots: 2 z-cols x 8 batches x 64 k, weights from regs ----
        ull acc[2][8];
#pragma unroll
        for (int j = 0; j < 2; ++j)
#pragma unroll
            for (int bi = 0; bi < 8; ++bi) acc[j][bi] = 0ull;

#pragma unroll 4
        for (int kk = 0; kk < 64; kk += 4) {
            ull w0a = wreg[0][kk >> 1], w0b = wreg[0][(kk >> 1) + 1];
            ull w1a = wreg[1][kk >> 1], w1b = wreg[1][(kk >> 1) + 1];
#pragma unroll
            for (int bi = 0; bi < 8; ++bi) {
                float4 hv = *(const float4*)&h_s[bi * HST + k0 + kk];  // bcast
                ull h01 = ((const ull*)&hv)[0], h23 = ((const ull*)&hv)[1];
                acc[0][bi] = fma2(h01, w0a, acc[0][bi]);
                acc[0][bi] = fma2(h23, w0b, acc[0][bi]);
                acc[1][bi] = fma2(h01, w1a, acc[1][bi]);
                acc[1][bi] = fma2(h23, w1b, acc[1][bi]);
            }
        }

        // ---- hadd over k-parity, stash partials ----
#pragma unroll
        for (int bi = 0; bi < 8; ++bi) {
            float2 pr;
            float2 a0 = *(float2*)&acc[0][bi];
            float2 a1 = *(float2*)&acc[1][bi];
            pr.x = a0.x + a0.y;
            pr.y = a1.x + a1.y;
            *(float2*)&part[(ko * 8 + bi) * PST + zct] = pr;
        }
        __syncthreads();

        // ---- reduce 8 k-octants + xp + bias -> z ----
        {
            float s0 = bsz0 + xpv.x;
            float s1 = bsz1 + xpv.y;
#pragma unroll
            for (int o = 0; o < 8; ++o) {
                float2 p = *(const float2*)&part[(o * 8 + rb) * PST + zc0r];
                s0 += p.x;
                s1 += p.y;
            }
            z_s[zc0r * 9 + rb]       = s0;
            z_s[(zc0r + 1) * 9 + rb] = s1;
        }
        __syncthreads();

        // ---- gates: 128 threads = 8 b x 16 cols ----
        if (tid < 128) {
            int b = tid >> 4, j = tid & 15;
            float zi = z_s[j * 9 + b];
            float zf = z_s[(16 + j) * 9 + b];
            float zg = z_s[(32 + j) * 9 + b];
            float zo = z_s[(48 + j) * 9 + b];
            float cn = sigf(zf) * c_s[b * 16 + j] + sigf(zi) * tanhf_fast(zg);
            float hn = sigf(zo) * tanhf_fast(cn);
            c_s[b * 16 + j] = cn;
            g_h[par ^ 1][(gb0 + b) * H_ + col0 + j] = hn;
            __stcs(&out[((size_t)(gb0 + b) * T_ + t) * H_ + col0 + j], hn);
        }
        __syncthreads();

        // ---- grid barrier ----
        if (tid == 0) {
            red_add_release(&g_ctr, 1u);
            unsigned int tgt = (unsigned int)(t + 1) * nblk;
            while (ld_acquire(&g_ctr) < tgt) { }
        }
        __syncthreads();
        par ^= 1;
    }
}

// =====================================================================
// launch
// =====================================================================
extern "C" void kernel_launch(void* const* d_in, const int* in_sizes, int n_in,
                              void* d_out, int out_size) {
    const float* inputs = (const float*)d_in[0];
    // d_in[1] = input_paddings (unused: all tokens valid)
    const float* c0   = (const float*)d_in[2];
    const float* h0   = (const float*)d_in[3];
    const float* Wi   = (const float*)d_in[4];
    const float* Wh   = (const float*)d_in[5];
    const float* bias = (const float*)d_in[6];
    float* out = (float*)d_out;

    dim3 g1(G4_ / BN, (B_ * T_) / BM);   // 16 x 512
    gemm_xproj<<<g1, 256>>>(inputs, Wi);
    init_kernel<<<64, 256>>>(h0);
    lstm_seq<<<128, 256>>>(c0, bias, Wh, out);
}